// round 3
// baseline (speedup 1.0000x reference)
#include <cuda_runtime.h>
#include <math.h>

#define BATCH 16384
#define D_IN  1711
#define ATANH_LIM (1.0f - 1e-5f)
#define MAXNORM   (1.0f - 4e-3f)

// ---------------- scratch (static device globals; no allocation) ----------------
__device__ float g_Xd[BATCH * D_IN];     // drug  preproc [B,1711]
__device__ float g_Xt[BATCH * D_IN];     // target preproc [B,1711]
__device__ float g_MXd[BATCH * 1024];    // gemm scratch drug
__device__ float g_MXt[BATCH * 1024];    // gemm scratch target
__device__ float g_Yd[BATCH * 1024];     // activations drug
__device__ float g_Yt[BATCH * 1024];     // activations target
__device__ float g_nd[BATCH];            // row norms drug
__device__ float g_nt[BATCH];            // row norms target
__device__ float g_mid[BATCH * 256];
__device__ float g_nmid[BATCH];

// ---------------- block reduction (256 threads) ----------------
__device__ __forceinline__ float blockReduceSum(float v, float* red)
{
    int lane = threadIdx.x & 31;
    int w    = threadIdx.x >> 5;
    #pragma unroll
    for (int o = 16; o > 0; o >>= 1) v += __shfl_xor_sync(0xffffffffu, v, o);
    __syncthreads();                 // protect red from previous call's readers
    if (lane == 0) red[w] = v;
    __syncthreads();
    float s = 0.f;
    #pragma unroll
    for (int i = 0; i < 8; i++) s += red[i];
    return s;                        // broadcast to all threads
}

// ---------------- preprocess: per-row zscore(segments) + concat + expmap0 ----------------
__global__ void pre_kernel(const float* __restrict__ s0, int d0,
                           const float* __restrict__ s1, int d1,
                           const float* __restrict__ s2, int d2,
                           const float* __restrict__ s3, int d3,
                           float* __restrict__ X, float* __restrict__ xn)
{
    __shared__ float buf[D_IN];
    __shared__ float red[32];
    int row = blockIdx.x, tid = threadIdx.x;
    const float* segs[4] = {s0, s1, s2, s3};
    int lens[4] = {d0, d1, d2, d3};
    int off = 0;
    for (int s = 0; s < 4; s++) {
        int d = lens[s];
        if (d == 0) continue;
        const float* p = segs[s] + (size_t)row * d;
        float sum = 0.f;
        for (int i = tid; i < d; i += 256) { float v = p[i]; buf[off + i] = v; sum += v; }
        sum = blockReduceSum(sum, red);
        float mean = sum / (float)d;
        float sq = 0.f;
        for (int i = tid; i < d; i += 256) { float v = buf[off + i] - mean; sq += v * v; }
        sq = blockReduceSum(sq, red);
        float sd  = sqrtf(sq / (float)(d - 1));       // ddof=1
        float inv = 1.f / (sd + 1e-8f);
        for (int i = tid; i < d; i += 256) buf[off + i] = (buf[off + i] - mean) * inv;
        off += d;
    }
    __syncthreads();
    float nn2 = 0.f;
    for (int i = tid; i < D_IN; i += 256) { float v = buf[i]; nn2 += v * v; }
    nn2 = blockReduceSum(nn2, red);
    float nrm = sqrtf(nn2);
    float n  = fmaxf(nrm, 1e-15f);
    float sc = tanhf(n) / n;                           // expmap0
    float* xo = X + (size_t)row * D_IN;
    for (int i = tid; i < D_IN; i += 256) xo[i] = sc * buf[i];
    if (tid == 0) xn[row] = sc * nrm;
}

// ---------------- fp32 SGEMM: C[M,N] = A[M,K] @ B[K,N], 128x128x8, 8x8 microtile ----------------
__global__ __launch_bounds__(256) void sgemm_kernel(const float* __restrict__ A,
                                                    const float* __restrict__ B,
                                                    float* __restrict__ C,
                                                    int M, int N, int K)
{
    __shared__ float As[8][128];
    __shared__ float Bs[8][128];
    int tid = threadIdx.x;
    int tx = tid & 15, ty = tid >> 4;
    int aRow = tid >> 1;            // 0..127
    int aCol = (tid & 1) << 2;      // 0 or 4
    int bRow = tid >> 5;            // 0..7
    int bCol = (tid & 31) << 2;     // 0..124
    const float* Ab = A + (size_t)blockIdx.y * 128 * K;
    const float* Bb = B + (size_t)blockIdx.x * 128;
    float acc[8][8];
    #pragma unroll
    for (int i = 0; i < 8; i++)
        #pragma unroll
        for (int j = 0; j < 8; j++) acc[i][j] = 0.f;

    for (int k0 = 0; k0 < K; k0 += 8) {
        #pragma unroll
        for (int i = 0; i < 4; i++) {
            int kk = k0 + aCol + i;
            As[aCol + i][aRow] = (kk < K) ? Ab[(size_t)aRow * K + kk] : 0.f;
        }
        {
            int kk = k0 + bRow;
            if (kk < K) {
                float4 v = *reinterpret_cast<const float4*>(Bb + (size_t)kk * N + bCol);
                Bs[bRow][bCol + 0] = v.x; Bs[bRow][bCol + 1] = v.y;
                Bs[bRow][bCol + 2] = v.z; Bs[bRow][bCol + 3] = v.w;
            } else {
                Bs[bRow][bCol + 0] = 0.f; Bs[bRow][bCol + 1] = 0.f;
                Bs[bRow][bCol + 2] = 0.f; Bs[bRow][bCol + 3] = 0.f;
            }
        }
        __syncthreads();
        #pragma unroll
        for (int k = 0; k < 8; k++) {
            float4 a0 = *reinterpret_cast<const float4*>(&As[k][ty * 8]);
            float4 a1 = *reinterpret_cast<const float4*>(&As[k][ty * 8 + 4]);
            float4 b0 = *reinterpret_cast<const float4*>(&Bs[k][tx * 8]);
            float4 b1 = *reinterpret_cast<const float4*>(&Bs[k][tx * 8 + 4]);
            float a[8] = {a0.x, a0.y, a0.z, a0.w, a1.x, a1.y, a1.z, a1.w};
            float b[8] = {b0.x, b0.y, b0.z, b0.w, b1.x, b1.y, b1.z, b1.w};
            #pragma unroll
            for (int i = 0; i < 8; i++)
                #pragma unroll
                for (int j = 0; j < 8; j++)
                    acc[i][j] = fmaf(a[i], b[j], acc[i][j]);
        }
        __syncthreads();
    }
    float* Cb = C + (size_t)(blockIdx.y * 128 + ty * 8) * N + blockIdx.x * 128 + tx * 8;
    #pragma unroll
    for (int i = 0; i < 8; i++) {
        float4 v0 = make_float4(acc[i][0], acc[i][1], acc[i][2], acc[i][3]);
        float4 v1 = make_float4(acc[i][4], acc[i][5], acc[i][6], acc[i][7]);
        *reinterpret_cast<float4*>(Cb + (size_t)i * N)     = v0;
        *reinterpret_cast<float4*>(Cb + (size_t)i * N + 4) = v1;
    }
}

// ---------------- hyperbolic epilogue: hlinear tail (+ optional mobius_tanh) ----------------
template<int N, bool DO_TANH>
__global__ void epi_kernel(const float* __restrict__ MX, const float* __restrict__ bvec,
                           const float* __restrict__ xn_in,
                           float* __restrict__ Xout, float* __restrict__ xn_out)
{
    constexpr int T = 256;
    constexpr int C = N / T;
    __shared__ float red[32];
    int row = blockIdx.x, tid = threadIdx.x;
    const float* mx = MX + (size_t)row * N;
    float m[C], b[C];
    float s_mm = 0.f, s_mb = 0.f, s_bb = 0.f;
    #pragma unroll
    for (int i = 0; i < C; i++) {
        int idx = tid + i * T;
        m[i] = mx[idx]; b[i] = bvec[idx];
        s_mm += m[i] * m[i]; s_mb += m[i] * b[i]; s_bb += b[i] * b[i];
    }
    s_mm = blockReduceSum(s_mm, red);
    s_mb = blockReduceSum(s_mb, red);
    s_bb = blockReduceSum(s_bb, red);

    // mobius_matvec tail + projx
    float xn  = fmaxf(xn_in[row], 1e-15f);
    float mxn = fmaxf(sqrtf(s_mm), 1e-15f);
    float t   = tanhf((mxn / xn) * atanhf(fminf(xn, ATANH_LIM)));
    float tc  = fminf(t, MAXNORM);       // projx clamp (norm == t)
    float s1  = tc / mxn;
    // mobius_add with bias b
    float x2 = tc * tc, xy = s1 * s_mb, y2 = s_bb;
    float den = fmaxf(1.f + 2.f * xy + x2 * y2, 1e-15f);
    float ca = (1.f + 2.f * xy + y2) * s1 / den;
    float cb = (1.f - x2) / den;
    float s_zz = 0.f;
    #pragma unroll
    for (int i = 0; i < C; i++) { m[i] = ca * m[i] + cb * b[i]; s_zz += m[i] * m[i]; }
    s_zz = blockReduceSum(s_zz, red);
    float znp = sqrtf(s_zz);
    float zn  = fmaxf(znp, 1e-15f);
    float sc  = (zn > MAXNORM) ? (MAXNORM / zn) : 1.f;   // projx
    float outn = sc * znp;
    float* xo = Xout + (size_t)row * N;
    if (!DO_TANH) {
        #pragma unroll
        for (int i = 0; i < C; i++) xo[tid + i * T] = sc * m[i];
        if (tid == 0) xn_out[row] = outn;
    } else {
        // mobius_tanh: projx(expmap0(tanh(logmap0(z'))))
        float nzn = fmaxf(outn, 1e-15f);
        float lsc = atanhf(fminf(nzn, ATANH_LIM)) / nzn * sc;
        float s_vv = 0.f;
        #pragma unroll
        for (int i = 0; i < C; i++) { m[i] = tanhf(lsc * m[i]); s_vv += m[i] * m[i]; }
        s_vv = blockReduceSum(s_vv, red);
        float vnp = sqrtf(s_vv);
        float vn  = fmaxf(vnp, 1e-15f);
        float esc = tanhf(vn) / vn;                  // expmap0
        float en  = esc * vnp;
        float pn  = fmaxf(en, 1e-15f);
        float psc = (pn > MAXNORM) ? (MAXNORM / pn) : 1.f;
        float fsc = psc * esc;
        #pragma unroll
        for (int i = 0; i < C; i++) xo[tid + i * T] = fsc * m[i];
        if (tid == 0) xn_out[row] = fsc * vnp;
    }
}

// ---------------- mid = projx(mobius_add(0.27 (x) head, 0.73 (x) tail)) ----------------
__global__ void combine_kernel(const float* __restrict__ H, const float* __restrict__ Tl,
                               float* __restrict__ mid, float* __restrict__ midn)
{
    __shared__ float red[32];
    int row = blockIdx.x, tid = threadIdx.x;       // 256 threads, dim 256
    float h = H[(size_t)row * 256 + tid];
    float t = Tl[(size_t)row * 256 + tid];
    float shh = blockReduceSum(h * h, red);
    float stt = blockReduceSum(t * t, red);
    float sht = blockReduceSum(h * t, red);
    float hn = fmaxf(sqrtf(shh), 1e-15f);
    float tn = fmaxf(sqrtf(stt), 1e-15f);
    float th = tanhf(0.27f * atanhf(fminf(hn, ATANH_LIM)));
    float tt = tanhf(0.73f * atanhf(fminf(tn, ATANH_LIM)));
    float ah = th / hn, at = tt / tn;
    float x2 = th * th, y2 = tt * tt, xy = ah * at * sht;
    float den = fmaxf(1.f + 2.f * xy + x2 * y2, 1e-15f);
    float ca = (1.f + 2.f * xy + y2) * ah / den;
    float cb = (1.f - x2) * at / den;
    float z = ca * h + cb * t;
    float szz = blockReduceSum(z * z, red);
    float znp = sqrtf(szz);
    float zn  = fmaxf(znp, 1e-15f);
    float sc  = (zn > MAXNORM) ? (MAXNORM / zn) : 1.f;
    mid[(size_t)row * 256 + tid] = sc * z;
    if (tid == 0) midn[row] = sc * znp;
}

// ---------------- small MLP (256->64->32->2), one CTA handles 8 rows ----------------
__device__ void matvec_sm(const float* x, int K, const float* __restrict__ W, int n,
                          float* out, float* part)
{
    int tid = threadIdx.x;
    int col = tid % n;
    int q   = tid / n;
    int nch = 256 / n;
    float p = 0.f;
    for (int k = q; k < K; k += nch) p += x[k] * W[k * n + col];
    __syncthreads();
    part[tid] = p;
    __syncthreads();
    for (int s = nch / 2; s > 0; s >>= 1) {
        if (q < s) part[q * n + col] += part[(q + s) * n + col];
        __syncthreads();
    }
    if (tid < n) out[tid] = part[tid];
    __syncthreads();
}

__device__ float hlin_epi_sm(float* v, int n, const float* __restrict__ b, float xn,
                             bool do_tanh, float* red)
{
    int tid = threadIdx.x;
    float mi = (tid < n) ? v[tid] : 0.f;
    float bi = (tid < n) ? b[tid] : 0.f;
    float s_mm = blockReduceSum(mi * mi, red);
    float s_mb = blockReduceSum(mi * bi, red);
    float s_bb = blockReduceSum(bi * bi, red);
    xn = fmaxf(xn, 1e-15f);
    float mxn = fmaxf(sqrtf(s_mm), 1e-15f);
    float t  = tanhf((mxn / xn) * atanhf(fminf(xn, ATANH_LIM)));
    float tc = fminf(t, MAXNORM);
    float s1 = tc / mxn;
    float x2 = tc * tc, xy = s1 * s_mb, y2 = s_bb;
    float den = fmaxf(1.f + 2.f * xy + x2 * y2, 1e-15f);
    float ca = (1.f + 2.f * xy + y2) * s1 / den;
    float cb = (1.f - x2) / den;
    float z = ca * mi + cb * bi;
    float s_zz = blockReduceSum(z * z, red);
    float znp = sqrtf(s_zz), zn = fmaxf(znp, 1e-15f);
    float sc = (zn > MAXNORM) ? (MAXNORM / zn) : 1.f;
    float nn = sc * znp;
    if (do_tanh) {
        float nzn = fmaxf(nn, 1e-15f);
        float lsc = atanhf(fminf(nzn, ATANH_LIM)) / nzn * sc;
        float vi = tanhf(lsc * z);
        float s_vv = blockReduceSum(vi * vi, red);
        float vnp = sqrtf(s_vv), vn = fmaxf(vnp, 1e-15f);
        float esc = tanhf(vn) / vn;
        float en  = esc * vnp;
        float pn  = fmaxf(en, 1e-15f);
        float psc = (pn > MAXNORM) ? (MAXNORM / pn) : 1.f;
        if (tid < n) v[tid] = psc * esc * vi;
        nn = psc * esc * vnp;
    } else {
        if (tid < n) v[tid] = sc * z;
    }
    __syncthreads();
    return nn;
}

#define MLP_ROWS 8
__global__ void mlp_kernel(const float* __restrict__ mid, const float* __restrict__ midn,
                           const float* __restrict__ Wm1, const float* __restrict__ bm1,
                           const float* __restrict__ Wm2, const float* __restrict__ bm2,
                           const float* __restrict__ Wm3, const float* __restrict__ bm3,
                           float* __restrict__ out)
{
    __shared__ float sx[256];
    __shared__ float part[256];
    __shared__ float va[64];
    __shared__ float vb[32];
    __shared__ float vc[2];
    __shared__ float red[32];
    int tid = threadIdx.x;
    int r0 = blockIdx.x * MLP_ROWS;
    for (int r = r0; r < r0 + MLP_ROWS; r++) {
        sx[tid] = mid[(size_t)r * 256 + tid];
        float xn = midn[r];
        __syncthreads();
        matvec_sm(sx, 256, Wm1, 64, va, part);
        xn = hlin_epi_sm(va, 64, bm1, xn, true, red);
        matvec_sm(va, 64, Wm2, 32, vb, part);
        xn = hlin_epi_sm(vb, 32, bm2, xn, true, red);
        matvec_sm(vb, 32, Wm3, 2, vc, part);
        xn = hlin_epi_sm(vc, 2, bm3, xn, false, red);
        if (tid < 2) out[(size_t)r * 2 + tid] = vc[tid];
        __syncthreads();
    }
}

// ---------------- host orchestration ----------------
static void run_branch(const float* X, const float* W1, const float* b1,
                       const float* W2, const float* b2,
                       const float* W3, const float* b3,
                       float* MX, float* Y, float* nrm)
{
    const int B = BATCH;
    {   dim3 g(1024 / 128, B / 128);
        sgemm_kernel<<<g, 256>>>(X, W1, MX, B, 1024, D_IN); }
    epi_kernel<1024, true><<<B, 256>>>(MX, b1, nrm, Y, nrm);
    {   dim3 g(512 / 128, B / 128);
        sgemm_kernel<<<g, 256>>>(Y, W2, MX, B, 512, 1024); }
    epi_kernel<512, true><<<B, 256>>>(MX, b2, nrm, Y, nrm);
    {   dim3 g(256 / 128, B / 128);
        sgemm_kernel<<<g, 256>>>(Y, W3, MX, B, 256, 512); }
    epi_kernel<256, false><<<B, 256>>>(MX, b3, nrm, Y, nrm);  // Y now holds head/tail [B,256]
}

extern "C" void kernel_launch(void* const* d_in, const int* in_sizes, int n_in,
                              void* d_out, int out_size)
{
    const float* dcb  = (const float*)d_in[0];
    const float* dpc  = (const float*)d_in[1];
    const float* dmac = (const float*)d_in[2];
    const float* decf = (const float*)d_in[3];
    const float* tesm = (const float*)d_in[4];
    const float* tpc  = (const float*)d_in[5];
    const float* tmer = (const float*)d_in[6];
    const float* Wd1 = (const float*)d_in[7];  const float* bd1 = (const float*)d_in[8];
    const float* Wd2 = (const float*)d_in[9];  const float* bd2 = (const float*)d_in[10];
    const float* Wd3 = (const float*)d_in[11]; const float* bd3 = (const float*)d_in[12];
    const float* Wt1 = (const float*)d_in[13]; const float* bt1 = (const float*)d_in[14];
    const float* Wt2 = (const float*)d_in[15]; const float* bt2 = (const float*)d_in[16];
    const float* Wt3 = (const float*)d_in[17]; const float* bt3 = (const float*)d_in[18];
    const float* Wm1 = (const float*)d_in[19]; const float* bm1 = (const float*)d_in[20];
    const float* Wm2 = (const float*)d_in[21]; const float* bm2 = (const float*)d_in[22];
    const float* Wm3 = (const float*)d_in[23]; const float* bm3 = (const float*)d_in[24];

    float *Xd, *Xt, *MXd, *MXt, *Yd, *Yt, *nd, *nt, *mid, *nmid;
    cudaGetSymbolAddress((void**)&Xd,  g_Xd);
    cudaGetSymbolAddress((void**)&Xt,  g_Xt);
    cudaGetSymbolAddress((void**)&MXd, g_MXd);
    cudaGetSymbolAddress((void**)&MXt, g_MXt);
    cudaGetSymbolAddress((void**)&Yd,  g_Yd);
    cudaGetSymbolAddress((void**)&Yt,  g_Yt);
    cudaGetSymbolAddress((void**)&nd,  g_nd);
    cudaGetSymbolAddress((void**)&nt,  g_nt);
    cudaGetSymbolAddress((void**)&mid, g_mid);
    cudaGetSymbolAddress((void**)&nmid, g_nmid);

    const int B = BATCH;
    // preprocess (zscore + concat + expmap0) -> X, row norms
    pre_kernel<<<B, 256>>>(dcb, 768, dpc, 11, dmac, 167, decf, 765, Xd, nd);
    pre_kernel<<<B, 256>>>(tesm, 1280, tpc, 11, tmer, 420, nullptr, 0, Xt, nt);

    run_branch(Xd, Wd1, bd1, Wd2, bd2, Wd3, bd3, MXd, Yd, nd);   // head -> Yd
    run_branch(Xt, Wt1, bt1, Wt2, bt2, Wt3, bt3, MXt, Yt, nt);   // tail -> Yt

    combine_kernel<<<B, 256>>>(Yd, Yt, mid, nmid);

    mlp_kernel<<<B / MLP_ROWS, 256>>>(mid, nmid, Wm1, bm1, Wm2, bm2, Wm3, bm3,
                                      (float*)d_out);
}

// round 7
// speedup vs baseline: 1.5698x; 1.5698x over previous
#include <cuda_runtime.h>
#include <math.h>
#include <stdint.h>

#define BATCH 16384
#define D_IN  1711
#define KPAD  1712
#define ATANH_LIM (1.0f - 1e-5f)
#define MAXNORM   (1.0f - 4e-3f)

// ---------------- scratch (static device globals; no allocation) ----------------
__device__ float g_Xd[BATCH * KPAD];     // drug  preproc [B,1712] (padded)
__device__ float g_Xt[BATCH * KPAD];     // target preproc [B,1712] (padded)
__device__ float g_Wd1p[KPAD * 1024];    // padded Wd1
__device__ float g_Wt1p[KPAD * 1024];    // padded Wt1
__device__ float g_MXd[BATCH * 1024];    // gemm scratch drug
__device__ float g_MXt[BATCH * 1024];    // gemm scratch target
__device__ float g_Yd[BATCH * 1024];     // activations drug
__device__ float g_Yt[BATCH * 1024];     // activations target
__device__ float g_nd[BATCH];            // row norms drug
__device__ float g_nt[BATCH];            // row norms target
__device__ float g_mid[BATCH * 256];
__device__ float g_nmid[BATCH];

// ---------------- block reduction (256 threads) ----------------
__device__ __forceinline__ float blockReduceSum(float v, float* red)
{
    int lane = threadIdx.x & 31;
    int w    = threadIdx.x >> 5;
    #pragma unroll
    for (int o = 16; o > 0; o >>= 1) v += __shfl_xor_sync(0xffffffffu, v, o);
    __syncthreads();                 // protect red from previous call's readers
    if (lane == 0) red[w] = v;
    __syncthreads();
    float s = 0.f;
    #pragma unroll
    for (int i = 0; i < 8; i++) s += red[i];
    return s;                        // broadcast to all threads
}

// ---------------- preprocess: per-row zscore(segments) + concat + expmap0 ----------------
__global__ void pre_kernel(const float* __restrict__ s0, int d0,
                           const float* __restrict__ s1, int d1,
                           const float* __restrict__ s2, int d2,
                           const float* __restrict__ s3, int d3,
                           float* __restrict__ X, float* __restrict__ xn)
{
    __shared__ float buf[D_IN];
    __shared__ float red[32];
    int row = blockIdx.x, tid = threadIdx.x;
    const float* segs[4] = {s0, s1, s2, s3};
    int lens[4] = {d0, d1, d2, d3};
    int off = 0;
    for (int s = 0; s < 4; s++) {
        int d = lens[s];
        if (d == 0) continue;
        const float* p = segs[s] + (size_t)row * d;
        float sum = 0.f;
        for (int i = tid; i < d; i += 256) { float v = p[i]; buf[off + i] = v; sum += v; }
        sum = blockReduceSum(sum, red);
        float mean = sum / (float)d;
        float sq = 0.f;
        for (int i = tid; i < d; i += 256) { float v = buf[off + i] - mean; sq += v * v; }
        sq = blockReduceSum(sq, red);
        float sd  = sqrtf(sq / (float)(d - 1));       // ddof=1
        float inv = 1.f / (sd + 1e-8f);
        for (int i = tid; i < d; i += 256) buf[off + i] = (buf[off + i] - mean) * inv;
        off += d;
    }
    __syncthreads();
    float nn2 = 0.f;
    for (int i = tid; i < D_IN; i += 256) { float v = buf[i]; nn2 += v * v; }
    nn2 = blockReduceSum(nn2, red);
    float nrm = sqrtf(nn2);
    float n  = fmaxf(nrm, 1e-15f);
    float sc = tanhf(n) / n;                           // expmap0
    float* xo = X + (size_t)row * KPAD;
    for (int i = tid; i < D_IN; i += 256) xo[i] = sc * buf[i];
    if (tid == 0) { xo[D_IN] = 0.f; xn[row] = sc * nrm; }   // zero pad col
}

// ---------------- weight pad: [1711,N] -> [1712,N] with zero last row ----------------
__global__ void padw_kernel(const float* __restrict__ W, float* __restrict__ Wp, int N)
{
    int idx = blockIdx.x * 256 + threadIdx.x;
    int tot = KPAD * N;
    if (idx < tot) {
        int k = idx / N;
        Wp[idx] = (k < D_IN) ? W[idx] : 0.f;
    }
}

// ---------------- 3xtf32 tensor-core GEMM: C[M,N] = A[M,K] @ B[K,N] ----------------
// 128x128x16 tile, 8 warps (4M x 2N), warp tile 32x64, m16n8k8 tf32 MMA.
#define BM 128
#define BN 128
#define BK 16
#define LDA 132
#define LDB 132

__device__ __forceinline__ void split_tf32(float x, uint32_t& hi, uint32_t& lo)
{
    uint32_t h = __float_as_uint(x) & 0xFFFFE000u;
    hi = h;
    lo = __float_as_uint(x - __uint_as_float(h));
}

__device__ __forceinline__ void mma_tf32(float* c, const uint32_t* a, const uint32_t* b)
{
    asm volatile(
        "mma.sync.aligned.m16n8k8.row.col.f32.tf32.tf32.f32 "
        "{%0,%1,%2,%3}, {%4,%5,%6,%7}, {%8,%9}, {%0,%1,%2,%3};\n"
        : "+f"(c[0]), "+f"(c[1]), "+f"(c[2]), "+f"(c[3])
        : "r"(a[0]), "r"(a[1]), "r"(a[2]), "r"(a[3]), "r"(b[0]), "r"(b[1]));
}

__global__ __launch_bounds__(256) void mma_gemm(const float* __restrict__ A,
                                                const float* __restrict__ B,
                                                float* __restrict__ C,
                                                int M, int N, int K)
{
    __shared__ float As[2][BK * LDA];   // As[buf][k*LDA + m]
    __shared__ float Bs[2][BK * LDB];   // Bs[buf][k*LDB + n]
    int tid  = threadIdx.x;
    int wid  = tid >> 5, lane = tid & 31;
    int g    = lane >> 2, tg = lane & 3;
    int m_warp = (wid & 3) * 32;
    int n_warp = (wid >> 2) * 64;
    const float* Ab = A + (size_t)(blockIdx.y * BM) * K;
    const float* Bb = B + blockIdx.x * BN;

    // LDG mapping: A 128x16 per chunk (2 float4/thread), B 16x128 (2 float4/thread)
    int ar = tid >> 2;            // row 0..63 (+64)
    int ac = (tid & 3) * 4;       // k-col group
    int br = tid >> 5;            // k-row 0..7 (+8)
    int bc = (tid & 31) * 4;      // n col

    float4 pa[2], pb[2];
    #pragma unroll
    for (int i = 0; i < 2; i++) {
        pa[i] = *(const float4*)(Ab + (size_t)(ar + i * 64) * K + ac);
        pb[i] = *(const float4*)(Bb + (size_t)(br + i * 8) * N + bc);
    }

    auto sts = [&](int buf) {
        #pragma unroll
        for (int i = 0; i < 2; i++) {
            int m = ar + i * 64;
            float* as = As[buf];
            as[(ac + 0) * LDA + m] = pa[i].x;
            as[(ac + 1) * LDA + m] = pa[i].y;
            as[(ac + 2) * LDA + m] = pa[i].z;
            as[(ac + 3) * LDA + m] = pa[i].w;
            *(float4*)&Bs[buf][(br + i * 8) * LDB + bc] = pb[i];
        }
    };

    sts(0);
    __syncthreads();

    float acc[2][8][4];
    #pragma unroll
    for (int mt = 0; mt < 2; mt++)
        #pragma unroll
        for (int nt = 0; nt < 8; nt++)
            #pragma unroll
            for (int i = 0; i < 4; i++) acc[mt][nt][i] = 0.f;

    int nk = K / BK;
    for (int kc = 0; kc < nk; kc++) {
        int buf = kc & 1;
        bool more = (kc + 1 < nk);
        if (more) {
            int koff = (kc + 1) * BK;
            #pragma unroll
            for (int i = 0; i < 2; i++) {
                pa[i] = *(const float4*)(Ab + (size_t)(ar + i * 64) * K + koff + ac);
                pb[i] = *(const float4*)(Bb + (size_t)(koff + br + i * 8) * N + bc);
            }
        }
        #pragma unroll
        for (int ks = 0; ks < 2; ks++) {
            int k0 = ks * 8;
            uint32_t ahi[2][4], alo[2][4], bhi[8][2], blo[8][2];
            #pragma unroll
            for (int mt = 0; mt < 2; mt++) {
                int mbase = m_warp + mt * 16;
                float a0 = As[buf][(k0 + tg) * LDA + mbase + g];
                float a1 = As[buf][(k0 + tg) * LDA + mbase + g + 8];
                float a2 = As[buf][(k0 + tg + 4) * LDA + mbase + g];
                float a3 = As[buf][(k0 + tg + 4) * LDA + mbase + g + 8];
                split_tf32(a0, ahi[mt][0], alo[mt][0]);
                split_tf32(a1, ahi[mt][1], alo[mt][1]);
                split_tf32(a2, ahi[mt][2], alo[mt][2]);
                split_tf32(a3, ahi[mt][3], alo[mt][3]);
            }
            #pragma unroll
            for (int nt = 0; nt < 8; nt++) {
                int nbase = n_warp + nt * 8;
                float b0 = Bs[buf][(k0 + tg) * LDB + nbase + g];
                float b1 = Bs[buf][(k0 + tg + 4) * LDB + nbase + g];
                split_tf32(b0, bhi[nt][0], blo[nt][0]);
                split_tf32(b1, bhi[nt][1], blo[nt][1]);
            }
            // overlap the next-buffer STS with the final burst of MMAs
            if (ks == 1 && more) sts(buf ^ 1);
            #pragma unroll
            for (int mt = 0; mt < 2; mt++)
                #pragma unroll
                for (int nt = 0; nt < 8; nt++) {
                    mma_tf32(acc[mt][nt], ahi[mt], bhi[nt]);
                    mma_tf32(acc[mt][nt], ahi[mt], blo[nt]);
                    mma_tf32(acc[mt][nt], alo[mt], bhi[nt]);
                }
        }
        __syncthreads();
    }

    float* Cb = C + (size_t)(blockIdx.y * BM + m_warp) * N + blockIdx.x * BN + n_warp;
    #pragma unroll
    for (int mt = 0; mt < 2; mt++)
        #pragma unroll
        for (int nt = 0; nt < 8; nt++) {
            int r0 = mt * 16 + g;
            int c0 = nt * 8 + 2 * tg;
            *(float2*)&Cb[(size_t)r0 * N + c0]       = make_float2(acc[mt][nt][0], acc[mt][nt][1]);
            *(float2*)&Cb[(size_t)(r0 + 8) * N + c0] = make_float2(acc[mt][nt][2], acc[mt][nt][3]);
        }
}

// ---------------- hyperbolic epilogue: hlinear tail (+ optional mobius_tanh) ----------------
template<int N, bool DO_TANH>
__global__ void epi_kernel(const float* __restrict__ MX, const float* __restrict__ bvec,
                           const float* __restrict__ xn_in,
                           float* __restrict__ Xout, float* __restrict__ xn_out)
{
    constexpr int T = 256;
    constexpr int C = N / T;
    __shared__ float red[32];
    int row = blockIdx.x, tid = threadIdx.x;
    const float* mx = MX + (size_t)row * N;
    float m[C], b[C];
    float s_mm = 0.f, s_mb = 0.f, s_bb = 0.f;
    #pragma unroll
    for (int i = 0; i < C; i++) {
        int idx = tid + i * T;
        m[i] = mx[idx]; b[i] = bvec[idx];
        s_mm += m[i] * m[i]; s_mb += m[i] * b[i]; s_bb += b[i] * b[i];
    }
    s_mm = blockReduceSum(s_mm, red);
    s_mb = blockReduceSum(s_mb, red);
    s_bb = blockReduceSum(s_bb, red);

    // mobius_matvec tail + projx
    float xn  = fmaxf(xn_in[row], 1e-15f);
    float mxn = fmaxf(sqrtf(s_mm), 1e-15f);
    float t   = tanhf((mxn / xn) * atanhf(fminf(xn, ATANH_LIM)));
    float tc  = fminf(t, MAXNORM);       // projx clamp (norm == t)
    float s1  = tc / mxn;
    // mobius_add with bias b
    float x2 = tc * tc, xy = s1 * s_mb, y2 = s_bb;
    float den = fmaxf(1.f + 2.f * xy + x2 * y2, 1e-15f);
    float ca = (1.f + 2.f * xy + y2) * s1 / den;
    float cb = (1.f - x2) / den;
    float s_zz = 0.f;
    #pragma unroll
    for (int i = 0; i < C; i++) { m[i] = ca * m[i] + cb * b[i]; s_zz += m[i] * m[i]; }
    s_zz = blockReduceSum(s_zz, red);
    float znp = sqrtf(s_zz);
    float zn  = fmaxf(znp, 1e-15f);
    float sc  = (zn > MAXNORM) ? (MAXNORM / zn) : 1.f;   // projx
    float outn = sc * znp;
    float* xo = Xout + (size_t)row * N;
    if (!DO_TANH) {
        #pragma unroll
        for (int i = 0; i < C; i++) xo[tid + i * T] = sc * m[i];
        if (tid == 0) xn_out[row] = outn;
    } else {
        // mobius_tanh: projx(expmap0(tanh(logmap0(z'))))
        float nzn = fmaxf(outn, 1e-15f);
        float lsc = atanhf(fminf(nzn, ATANH_LIM)) / nzn * sc;
        float s_vv = 0.f;
        #pragma unroll
        for (int i = 0; i < C; i++) { m[i] = tanhf(lsc * m[i]); s_vv += m[i] * m[i]; }
        s_vv = blockReduceSum(s_vv, red);
        float vnp = sqrtf(s_vv);
        float vn  = fmaxf(vnp, 1e-15f);
        float esc = tanhf(vn) / vn;                  // expmap0
        float en  = esc * vnp;
        float pn  = fmaxf(en, 1e-15f);
        float psc = (pn > MAXNORM) ? (MAXNORM / pn) : 1.f;
        float fsc = psc * esc;
        #pragma unroll
        for (int i = 0; i < C; i++) xo[tid + i * T] = fsc * m[i];
        if (tid == 0) xn_out[row] = fsc * vnp;
    }
}

// ---------------- mid = projx(mobius_add(0.27 (x) head, 0.73 (x) tail)) ----------------
__global__ void combine_kernel(const float* __restrict__ H, const float* __restrict__ Tl,
                               float* __restrict__ mid, float* __restrict__ midn)
{
    __shared__ float red[32];
    int row = blockIdx.x, tid = threadIdx.x;       // 256 threads, dim 256
    float h = H[(size_t)row * 256 + tid];
    float t = Tl[(size_t)row * 256 + tid];
    float shh = blockReduceSum(h * h, red);
    float stt = blockReduceSum(t * t, red);
    float sht = blockReduceSum(h * t, red);
    float hn = fmaxf(sqrtf(shh), 1e-15f);
    float tn = fmaxf(sqrtf(stt), 1e-15f);
    float th = tanhf(0.27f * atanhf(fminf(hn, ATANH_LIM)));
    float tt = tanhf(0.73f * atanhf(fminf(tn, ATANH_LIM)));
    float ah = th / hn, at = tt / tn;
    float x2 = th * th, y2 = tt * tt, xy = ah * at * sht;
    float den = fmaxf(1.f + 2.f * xy + x2 * y2, 1e-15f);
    float ca = (1.f + 2.f * xy + y2) * ah / den;
    float cb = (1.f - x2) * at / den;
    float z = ca * h + cb * t;
    float szz = blockReduceSum(z * z, red);
    float znp = sqrtf(szz);
    float zn  = fmaxf(znp, 1e-15f);
    float sc  = (zn > MAXNORM) ? (MAXNORM / zn) : 1.f;
    mid[(size_t)row * 256 + tid] = sc * z;
    if (tid == 0) midn[row] = sc * znp;
}

// ---------------- small MLP (256->64->32->2), one CTA handles 8 rows ----------------
__device__ void matvec_sm(const float* x, int K, const float* __restrict__ W, int n,
                          float* out, float* part)
{
    int tid = threadIdx.x;
    int col = tid % n;
    int q   = tid / n;
    int nch = 256 / n;
    float p = 0.f;
    for (int k = q; k < K; k += nch) p += x[k] * W[k * n + col];
    __syncthreads();
    part[tid] = p;
    __syncthreads();
    for (int s = nch / 2; s > 0; s >>= 1) {
        if (q < s) part[q * n + col] += part[(q + s) * n + col];
        __syncthreads();
    }
    if (tid < n) out[tid] = part[tid];
    __syncthreads();
}

__device__ float hlin_epi_sm(float* v, int n, const float* __restrict__ b, float xn,
                             bool do_tanh, float* red)
{
    int tid = threadIdx.x;
    float mi = (tid < n) ? v[tid] : 0.f;
    float bi = (tid < n) ? b[tid] : 0.f;
    float s_mm = blockReduceSum(mi * mi, red);
    float s_mb = blockReduceSum(mi * bi, red);
    float s_bb = blockReduceSum(bi * bi, red);
    xn = fmaxf(xn, 1e-15f);
    float mxn = fmaxf(sqrtf(s_mm), 1e-15f);
    float t  = tanhf((mxn / xn) * atanhf(fminf(xn, ATANH_LIM)));
    float tc = fminf(t, MAXNORM);
    float s1 = tc / mxn;
    float x2 = tc * tc, xy = s1 * s_mb, y2 = s_bb;
    float den = fmaxf(1.f + 2.f * xy + x2 * y2, 1e-15f);
    float ca = (1.f + 2.f * xy + y2) * s1 / den;
    float cb = (1.f - x2) / den;
    float z = ca * mi + cb * bi;
    float s_zz = blockReduceSum(z * z, red);
    float znp = sqrtf(s_zz), zn = fmaxf(znp, 1e-15f);
    float sc = (zn > MAXNORM) ? (MAXNORM / zn) : 1.f;
    float nn = sc * znp;
    if (do_tanh) {
        float nzn = fmaxf(nn, 1e-15f);
        float lsc = atanhf(fminf(nzn, ATANH_LIM)) / nzn * sc;
        float vi = tanhf(lsc * z);
        float s_vv = blockReduceSum(vi * vi, red);
        float vnp = sqrtf(s_vv), vn = fmaxf(vnp, 1e-15f);
        float esc = tanhf(vn) / vn;
        float en  = esc * vnp;
        float pn  = fmaxf(en, 1e-15f);
        float psc = (pn > MAXNORM) ? (MAXNORM / pn) : 1.f;
        if (tid < n) v[tid] = psc * esc * vi;
        nn = psc * esc * vnp;
    } else {
        if (tid < n) v[tid] = sc * z;
    }
    __syncthreads();
    return nn;
}

#define MLP_ROWS 8
__global__ void mlp_kernel(const float* __restrict__ mid, const float* __restrict__ midn,
                           const float* __restrict__ Wm1, const float* __restrict__ bm1,
                           const float* __restrict__ Wm2, const float* __restrict__ bm2,
                           const float* __restrict__ Wm3, const float* __restrict__ bm3,
                           float* __restrict__ out)
{
    __shared__ float sx[256];
    __shared__ float part[256];
    __shared__ float va[64];
    __shared__ float vb[32];
    __shared__ float vc[2];
    __shared__ float red[32];
    int tid = threadIdx.x;
    int r0 = blockIdx.x * MLP_ROWS;
    for (int r = r0; r < r0 + MLP_ROWS; r++) {
        sx[tid] = mid[(size_t)r * 256 + tid];
        float xn = midn[r];
        __syncthreads();
        matvec_sm(sx, 256, Wm1, 64, va, part);
        xn = hlin_epi_sm(va, 64, bm1, xn, true, red);
        matvec_sm(va, 64, Wm2, 32, vb, part);
        xn = hlin_epi_sm(vb, 32, bm2, xn, true, red);
        matvec_sm(vb, 32, Wm3, 2, vc, part);
        xn = hlin_epi_sm(vc, 2, bm3, xn, false, red);
        if (tid < 2) out[(size_t)r * 2 + tid] = vc[tid];
        __syncthreads();
    }
}

// ---------------- host orchestration ----------------
static void run_branch(const float* X, const float* W1p, const float* b1,
                       const float* W2, const float* b2,
                       const float* W3, const float* b3,
                       float* MX, float* Y, float* nrm)
{
    const int B = BATCH;
    {   dim3 g(1024 / BN, B / BM);
        mma_gemm<<<g, 256>>>(X, W1p, MX, B, 1024, KPAD); }
    epi_kernel<1024, true><<<B, 256>>>(MX, b1, nrm, Y, nrm);
    {   dim3 g(512 / BN, B / BM);
        mma_gemm<<<g, 256>>>(Y, W2, MX, B, 512, 1024); }
    epi_kernel<512, true><<<B, 256>>>(MX, b2, nrm, Y, nrm);
    {   dim3 g(256 / BN, B / BM);
        mma_gemm<<<g, 256>>>(Y, W3, MX, B, 256, 512); }
    epi_kernel<256, false><<<B, 256>>>(MX, b3, nrm, Y, nrm);  // Y now holds head/tail [B,256]
}

extern "C" void kernel_launch(void* const* d_in, const int* in_sizes, int n_in,
                              void* d_out, int out_size)
{
    const float* dcb  = (const float*)d_in[0];
    const float* dpc  = (const float*)d_in[1];
    const float* dmac = (const float*)d_in[2];
    const float* decf = (const float*)d_in[3];
    const float* tesm = (const float*)d_in[4];
    const float* tpc  = (const float*)d_in[5];
    const float* tmer = (const float*)d_in[6];
    const float* Wd1 = (const float*)d_in[7];  const float* bd1 = (const float*)d_in[8];
    const float* Wd2 = (const float*)d_in[9];  const float* bd2 = (const float*)d_in[10];
    const float* Wd3 = (const float*)d_in[11]; const float* bd3 = (const float*)d_in[12];
    const float* Wt1 = (const float*)d_in[13]; const float* bt1 = (const float*)d_in[14];
    const float* Wt2 = (const float*)d_in[15]; const float* bt2 = (const float*)d_in[16];
    const float* Wt3 = (const float*)d_in[17]; const float* bt3 = (const float*)d_in[18];
    const float* Wm1 = (const float*)d_in[19]; const float* bm1 = (const float*)d_in[20];
    const float* Wm2 = (const float*)d_in[21]; const float* bm2 = (const float*)d_in[22];
    const float* Wm3 = (const float*)d_in[23]; const float* bm3 = (const float*)d_in[24];

    float *Xd, *Xt, *MXd, *MXt, *Yd, *Yt, *nd, *nt, *mid, *nmid, *Wd1p, *Wt1p;
    cudaGetSymbolAddress((void**)&Xd,  g_Xd);
    cudaGetSymbolAddress((void**)&Xt,  g_Xt);
    cudaGetSymbolAddress((void**)&MXd, g_MXd);
    cudaGetSymbolAddress((void**)&MXt, g_MXt);
    cudaGetSymbolAddress((void**)&Yd,  g_Yd);
    cudaGetSymbolAddress((void**)&Yt,  g_Yt);
    cudaGetSymbolAddress((void**)&nd,  g_nd);
    cudaGetSymbolAddress((void**)&nt,  g_nt);
    cudaGetSymbolAddress((void**)&mid, g_mid);
    cudaGetSymbolAddress((void**)&nmid, g_nmid);
    cudaGetSymbolAddress((void**)&Wd1p, g_Wd1p);
    cudaGetSymbolAddress((void**)&Wt1p, g_Wt1p);

    const int B = BATCH;
    // pad first-layer weights into KPAD-row scratch
    {   int tot = KPAD * 1024;
        int gp = (tot + 255) / 256;
        padw_kernel<<<gp, 256>>>(Wd1, Wd1p, 1024);
        padw_kernel<<<gp, 256>>>(Wt1, Wt1p, 1024); }

    // preprocess (zscore + concat + expmap0) -> X (padded), row norms
    pre_kernel<<<B, 256>>>(dcb, 768, dpc, 11, dmac, 167, decf, 765, Xd, nd);
    pre_kernel<<<B, 256>>>(tesm, 1280, tpc, 11, tmer, 420, nullptr, 0, Xt, nt);

    run_branch(Xd, Wd1p, bd1, Wd2, bd2, Wd3, bd3, MXd, Yd, nd);   // head -> Yd
    run_branch(Xt, Wt1p, bt1, Wt2, bt2, Wt3, bt3, MXt, Yt, nt);   // tail -> Yt

    combine_kernel<<<B, 256>>>(Yd, Yt, mid, nmid);

    mlp_kernel<<<B / MLP_ROWS, 256>>>(mid, nmid, Wm1, bm1, Wm2, bm2, Wm3, bm3,
                                      (float*)d_out);
}

// round 9
// speedup vs baseline: 2.5329x; 1.6135x over previous
#include <cuda_runtime.h>
#include <cuda_fp16.h>
#include <math.h>
#include <stdint.h>

#define BATCH 16384
#define D_IN  1711
#define KP1   1728                  // K padded to multiple of 32
#define ATANH_LIM (1.0f - 1e-5f)
#define MAXNORM   (1.0f - 4e-3f)

// ---------------- scratch (static device globals; no allocation) ----------------
__device__ float g_Xd[BATCH * KP1];      // drug  preproc [B,1728] (padded)
__device__ float g_Xt[BATCH * KP1];      // target preproc [B,1728] (padded)
__device__ float g_Wd1t[1024 * KP1];     // W1^T padded  [N=1024][K=1728]
__device__ float g_Wt1t[1024 * KP1];
__device__ float g_Wd2t[512 * 1024];     // W2^T [512][1024]
__device__ float g_Wt2t[512 * 1024];
__device__ float g_Wd3t[256 * 512];      // W3^T [256][512]
__device__ float g_Wt3t[256 * 512];
__device__ float g_MXd[BATCH * 1024];
__device__ float g_MXt[BATCH * 1024];
__device__ float g_Yd[BATCH * 1024];
__device__ float g_Yt[BATCH * 1024];
__device__ float g_nd[BATCH];
__device__ float g_nt[BATCH];
__device__ float g_mid[BATCH * 256];
__device__ float g_nmid[BATCH];

// ---------------- block reduction (256 threads) ----------------
__device__ __forceinline__ float blockReduceSum(float v, float* red)
{
    int lane = threadIdx.x & 31;
    int w    = threadIdx.x >> 5;
    #pragma unroll
    for (int o = 16; o > 0; o >>= 1) v += __shfl_xor_sync(0xffffffffu, v, o);
    __syncthreads();
    if (lane == 0) red[w] = v;
    __syncthreads();
    float s = 0.f;
    #pragma unroll
    for (int i = 0; i < 8; i++) s += red[i];
    return s;
}

// ---------------- preprocess: per-row zscore(segments) + concat + expmap0 ----------------
__global__ void pre_kernel(const float* __restrict__ s0, int d0,
                           const float* __restrict__ s1, int d1,
                           const float* __restrict__ s2, int d2,
                           const float* __restrict__ s3, int d3,
                           float* __restrict__ X, float* __restrict__ xn)
{
    __shared__ float buf[D_IN];
    __shared__ float red[32];
    int row = blockIdx.x, tid = threadIdx.x;
    const float* segs[4] = {s0, s1, s2, s3};
    int lens[4] = {d0, d1, d2, d3};
    int off = 0;
    for (int s = 0; s < 4; s++) {
        int d = lens[s];
        if (d == 0) continue;
        const float* p = segs[s] + (size_t)row * d;
        float sum = 0.f;
        for (int i = tid; i < d; i += 256) { float v = p[i]; buf[off + i] = v; sum += v; }
        sum = blockReduceSum(sum, red);
        float mean = sum / (float)d;
        float sq = 0.f;
        for (int i = tid; i < d; i += 256) { float v = buf[off + i] - mean; sq += v * v; }
        sq = blockReduceSum(sq, red);
        float sd  = sqrtf(sq / (float)(d - 1));
        float inv = 1.f / (sd + 1e-8f);
        for (int i = tid; i < d; i += 256) buf[off + i] = (buf[off + i] - mean) * inv;
        off += d;
    }
    __syncthreads();
    float nn2 = 0.f;
    for (int i = tid; i < D_IN; i += 256) { float v = buf[i]; nn2 += v * v; }
    nn2 = blockReduceSum(nn2, red);
    float nrm = sqrtf(nn2);
    float n  = fmaxf(nrm, 1e-15f);
    float sc = tanhf(n) / n;                           // expmap0
    float* xo = X + (size_t)row * KP1;
    for (int i = tid; i < D_IN; i += 256) xo[i] = sc * buf[i];
    for (int i = D_IN + tid; i < KP1; i += 256) xo[i] = 0.f;   // zero pad cols
    if (tid == 0) xn[row] = sc * nrm;
}

// ---------------- weight transpose+pad: W[K,N] -> Wt[N,Kp] (zeros for k>=K) ----------------
__global__ void transpose_pad(const float* __restrict__ W, float* __restrict__ Wt,
                              int K, int N, int Kp)
{
    __shared__ float t[32][33];
    int kb = blockIdx.x * 32, nb = blockIdx.y * 32;
    #pragma unroll
    for (int i = 0; i < 32; i += 8) {
        int kk = kb + threadIdx.y + i;
        int nn = nb + threadIdx.x;
        t[threadIdx.y + i][threadIdx.x] =
            (kk < K && nn < N) ? W[(size_t)kk * N + nn] : 0.f;
    }
    __syncthreads();
    #pragma unroll
    for (int i = 0; i < 32; i += 8) {
        int nn = nb + threadIdx.y + i;
        int kk = kb + threadIdx.x;
        if (nn < N && kk < Kp)
            Wt[(size_t)nn * Kp + kk] = t[threadIdx.x][threadIdx.y + i];
    }
}

// ---------------- 3xfp16-split tensor GEMM: C[M,N] = A[M,K] @ Bt[N,K]^T ----------------
// CTA tile 128x128, K-stage 32, m16n8k16 fp16 MMA, fp32 accumulate.
// Hi/Lo split done ONCE at STS; inner loop is pure LDS + HMMA.
// Smem: per stage 4 arrays (Ah, Al, Bh, Bl), each [128 rows][20 half2-words].
#define LDH 20
#define STG_U32 (4 * 128 * LDH)          // 10240 words per stage
#define HSMEM (2 * STG_U32 * 4)          // 81920 bytes

__device__ __forceinline__ uint32_t pack_h2(float x, float y)
{
    __half2 h = __floats2half2_rn(x, y);
    return *reinterpret_cast<uint32_t*>(&h);
}

__device__ __forceinline__ void split4(const float4 v, uint32_t& h0, uint32_t& h1,
                                       uint32_t& l0, uint32_t& l1)
{
    float ax = __half2float(__float2half_rn(v.x));
    float ay = __half2float(__float2half_rn(v.y));
    float az = __half2float(__float2half_rn(v.z));
    float aw = __half2float(__float2half_rn(v.w));
    h0 = pack_h2(ax, ay); h1 = pack_h2(az, aw);
    l0 = pack_h2(v.x - ax, v.y - ay); l1 = pack_h2(v.z - az, v.w - aw);
}

__device__ __forceinline__ void mma_f16(float* c, const uint32_t* a, const uint32_t* b)
{
    asm volatile(
        "mma.sync.aligned.m16n8k16.row.col.f32.f16.f16.f32 "
        "{%0,%1,%2,%3}, {%4,%5,%6,%7}, {%8,%9}, {%0,%1,%2,%3};\n"
        : "+f"(c[0]), "+f"(c[1]), "+f"(c[2]), "+f"(c[3])
        : "r"(a[0]), "r"(a[1]), "r"(a[2]), "r"(a[3]), "r"(b[0]), "r"(b[1]));
}

__global__ __launch_bounds__(256) void hgemm(const float* __restrict__ A,
                                             const float* __restrict__ Bt,
                                             float* __restrict__ C, int N, int K)
{
    extern __shared__ __align__(16) uint32_t hs[];
    int tid = threadIdx.x;
    int wid = tid >> 5, lane = tid & 31;
    int g = lane >> 2, tg = lane & 3;
    int m_warp = (wid & 3) * 32;
    int n_warp = (wid >> 2) * 64;
    const float* Ab = A  + (size_t)(blockIdx.y * 128) * K;
    const float* Bb = Bt + (size_t)(blockIdx.x * 128) * K;

    float4 pa[4], pb[4];
    auto prefetch = [&](int k0) {
        #pragma unroll
        for (int i = 0; i < 4; i++) {
            int idx = tid + i * 256;           // 0..1023
            int row = idx >> 3, f4 = idx & 7;  // row 0..127, f4 0..7
            pa[i] = *(const float4*)(Ab + (size_t)row * K + k0 + f4 * 4);
            pb[i] = *(const float4*)(Bb + (size_t)row * K + k0 + f4 * 4);
        }
    };
    auto sts = [&](int s) {
        uint32_t* Ah = hs + s * STG_U32;
        uint32_t* Al = Ah + 2560;
        uint32_t* Bh = Ah + 5120;
        uint32_t* Bl = Ah + 7680;
        #pragma unroll
        for (int i = 0; i < 4; i++) {
            int idx = tid + i * 256;
            int row = idx >> 3, f4 = idx & 7;
            int base = row * LDH + f4 * 2;
            uint32_t h0, h1, l0, l1;
            split4(pa[i], h0, h1, l0, l1);
            Ah[base] = h0; Ah[base + 1] = h1; Al[base] = l0; Al[base + 1] = l1;
            split4(pb[i], h0, h1, l0, l1);
            Bh[base] = h0; Bh[base + 1] = h1; Bl[base] = l0; Bl[base + 1] = l1;
        }
    };

    prefetch(0);
    sts(0);
    __syncthreads();

    float acc[2][8][4];
    #pragma unroll
    for (int mt = 0; mt < 2; mt++)
        #pragma unroll
        for (int nt = 0; nt < 8; nt++)
            #pragma unroll
            for (int i = 0; i < 4; i++) acc[mt][nt][i] = 0.f;

    int nk = K / 32;
    for (int kc = 0; kc < nk; kc++) {
        int buf = kc & 1;
        bool more = (kc + 1 < nk);
        if (more) prefetch((kc + 1) * 32);
        const uint32_t* Ah = hs + buf * STG_U32;
        const uint32_t* Al = Ah + 2560;
        const uint32_t* Bh = Ah + 5120;
        const uint32_t* Bl = Ah + 7680;
        #pragma unroll
        for (int ks = 0; ks < 2; ks++) {
            int ck = ks * 8;                   // half2 col base for this k16
            uint32_t ah[2][4], al_[2][4], bh[8][2], bl[8][2];
            #pragma unroll
            for (int mt = 0; mt < 2; mt++) {
                int mb = m_warp + mt * 16;
                int r0 = (mb + g) * LDH, r1 = (mb + 8 + g) * LDH;
                ah[mt][0] = Ah[r0 + ck + tg];     ah[mt][1] = Ah[r1 + ck + tg];
                ah[mt][2] = Ah[r0 + ck + tg + 4]; ah[mt][3] = Ah[r1 + ck + tg + 4];
                al_[mt][0] = Al[r0 + ck + tg];     al_[mt][1] = Al[r1 + ck + tg];
                al_[mt][2] = Al[r0 + ck + tg + 4]; al_[mt][3] = Al[r1 + ck + tg + 4];
            }
            #pragma unroll
            for (int nt = 0; nt < 8; nt++) {
                int rb = (n_warp + nt * 8 + g) * LDH;
                bh[nt][0] = Bh[rb + ck + tg]; bh[nt][1] = Bh[rb + ck + tg + 4];
                bl[nt][0] = Bl[rb + ck + tg]; bl[nt][1] = Bl[rb + ck + tg + 4];
            }
            if (ks == 1 && more) sts(buf ^ 1);   // overlap STS with final MMA burst
            #pragma unroll
            for (int mt = 0; mt < 2; mt++)
                #pragma unroll
                for (int nt = 0; nt < 8; nt++) {
                    mma_f16(acc[mt][nt], ah[mt], bh[nt]);
                    mma_f16(acc[mt][nt], ah[mt], bl[nt]);
                    mma_f16(acc[mt][nt], al_[mt], bh[nt]);
                }
        }
        __syncthreads();
    }

    float* Cb = C + (size_t)(blockIdx.y * 128 + m_warp) * N + blockIdx.x * 128 + n_warp;
    #pragma unroll
    for (int mt = 0; mt < 2; mt++)
        #pragma unroll
        for (int nt = 0; nt < 8; nt++) {
            int r0 = mt * 16 + g;
            int c0 = nt * 8 + 2 * tg;
            *(float2*)&Cb[(size_t)r0 * N + c0]       = make_float2(acc[mt][nt][0], acc[mt][nt][1]);
            *(float2*)&Cb[(size_t)(r0 + 8) * N + c0] = make_float2(acc[mt][nt][2], acc[mt][nt][3]);
        }
}

// ---------------- hyperbolic epilogue: hlinear tail (+ optional mobius_tanh) ----------------
template<int N, bool DO_TANH>
__global__ void epi_kernel(const float* __restrict__ MX, const float* __restrict__ bvec,
                           const float* __restrict__ xn_in,
                           float* __restrict__ Xout, float* __restrict__ xn_out)
{
    constexpr int T = 256;
    constexpr int C = N / T;
    __shared__ float red[32];
    int row = blockIdx.x, tid = threadIdx.x;
    const float* mx = MX + (size_t)row * N;
    float m[C], b[C];
    float s_mm = 0.f, s_mb = 0.f, s_bb = 0.f;
    #pragma unroll
    for (int i = 0; i < C; i++) {
        int idx = tid + i * T;
        m[i] = mx[idx]; b[i] = bvec[idx];
        s_mm += m[i] * m[i]; s_mb += m[i] * b[i]; s_bb += b[i] * b[i];
    }
    s_mm = blockReduceSum(s_mm, red);
    s_mb = blockReduceSum(s_mb, red);
    s_bb = blockReduceSum(s_bb, red);

    float xn  = fmaxf(xn_in[row], 1e-15f);
    float mxn = fmaxf(sqrtf(s_mm), 1e-15f);
    float t   = tanhf((mxn / xn) * atanhf(fminf(xn, ATANH_LIM)));
    float tc  = fminf(t, MAXNORM);
    float s1  = tc / mxn;
    float x2 = tc * tc, xy = s1 * s_mb, y2 = s_bb;
    float den = fmaxf(1.f + 2.f * xy + x2 * y2, 1e-15f);
    float ca = (1.f + 2.f * xy + y2) * s1 / den;
    float cb = (1.f - x2) / den;
    float s_zz = 0.f;
    #pragma unroll
    for (int i = 0; i < C; i++) { m[i] = ca * m[i] + cb * b[i]; s_zz += m[i] * m[i]; }
    s_zz = blockReduceSum(s_zz, red);
    float znp = sqrtf(s_zz);
    float zn  = fmaxf(znp, 1e-15f);
    float sc  = (zn > MAXNORM) ? (MAXNORM / zn) : 1.f;
    float outn = sc * znp;
    float* xo = Xout + (size_t)row * N;
    if (!DO_TANH) {
        #pragma unroll
        for (int i = 0; i < C; i++) xo[tid + i * T] = sc * m[i];
        if (tid == 0) xn_out[row] = outn;
    } else {
        float nzn = fmaxf(outn, 1e-15f);
        float lsc = atanhf(fminf(nzn, ATANH_LIM)) / nzn * sc;
        float s_vv = 0.f;
        #pragma unroll
        for (int i = 0; i < C; i++) { m[i] = tanhf(lsc * m[i]); s_vv += m[i] * m[i]; }
        s_vv = blockReduceSum(s_vv, red);
        float vnp = sqrtf(s_vv);
        float vn  = fmaxf(vnp, 1e-15f);
        float esc = tanhf(vn) / vn;
        float en  = esc * vnp;
        float pn  = fmaxf(en, 1e-15f);
        float psc = (pn > MAXNORM) ? (MAXNORM / pn) : 1.f;
        float fsc = psc * esc;
        #pragma unroll
        for (int i = 0; i < C; i++) xo[tid + i * T] = fsc * m[i];
        if (tid == 0) xn_out[row] = fsc * vnp;
    }
}

// ---------------- mid = projx(mobius_add(0.27 (x) head, 0.73 (x) tail)) ----------------
__global__ void combine_kernel(const float* __restrict__ H, const float* __restrict__ Tl,
                               float* __restrict__ mid, float* __restrict__ midn)
{
    __shared__ float red[32];
    int row = blockIdx.x, tid = threadIdx.x;
    float h = H[(size_t)row * 256 + tid];
    float t = Tl[(size_t)row * 256 + tid];
    float shh = blockReduceSum(h * h, red);
    float stt = blockReduceSum(t * t, red);
    float sht = blockReduceSum(h * t, red);
    float hn = fmaxf(sqrtf(shh), 1e-15f);
    float tn = fmaxf(sqrtf(stt), 1e-15f);
    float th = tanhf(0.27f * atanhf(fminf(hn, ATANH_LIM)));
    float tt = tanhf(0.73f * atanhf(fminf(tn, ATANH_LIM)));
    float ah = th / hn, at = tt / tn;
    float x2 = th * th, y2 = tt * tt, xy = ah * at * sht;
    float den = fmaxf(1.f + 2.f * xy + x2 * y2, 1e-15f);
    float ca = (1.f + 2.f * xy + y2) * ah / den;
    float cb = (1.f - x2) * at / den;
    float z = ca * h + cb * t;
    float szz = blockReduceSum(z * z, red);
    float znp = sqrtf(szz);
    float zn  = fmaxf(znp, 1e-15f);
    float sc  = (zn > MAXNORM) ? (MAXNORM / zn) : 1.f;
    mid[(size_t)row * 256 + tid] = sc * z;
    if (tid == 0) midn[row] = sc * znp;
}

// ---------------- small MLP (256->64->32->2), one CTA handles 8 rows ----------------
__device__ void matvec_sm(const float* x, int K, const float* __restrict__ W, int n,
                          float* out, float* part)
{
    int tid = threadIdx.x;
    int col = tid % n;
    int q   = tid / n;
    int nch = 256 / n;
    float p = 0.f;
    for (int k = q; k < K; k += nch) p += x[k] * W[k * n + col];
    __syncthreads();
    part[tid] = p;
    __syncthreads();
    for (int s = nch / 2; s > 0; s >>= 1) {
        if (q < s) part[q * n + col] += part[(q + s) * n + col];
        __syncthreads();
    }
    if (tid < n) out[tid] = part[tid];
    __syncthreads();
}

__device__ float hlin_epi_sm(float* v, int n, const float* __restrict__ b, float xn,
                             bool do_tanh, float* red)
{
    int tid = threadIdx.x;
    float mi = (tid < n) ? v[tid] : 0.f;
    float bi = (tid < n) ? b[tid] : 0.f;
    float s_mm = blockReduceSum(mi * mi, red);
    float s_mb = blockReduceSum(mi * bi, red);
    float s_bb = blockReduceSum(bi * bi, red);
    xn = fmaxf(xn, 1e-15f);
    float mxn = fmaxf(sqrtf(s_mm), 1e-15f);
    float t  = tanhf((mxn / xn) * atanhf(fminf(xn, ATANH_LIM)));
    float tc = fminf(t, MAXNORM);
    float s1 = tc / mxn;
    float x2 = tc * tc, xy = s1 * s_mb, y2 = s_bb;
    float den = fmaxf(1.f + 2.f * xy + x2 * y2, 1e-15f);
    float ca = (1.f + 2.f * xy + y2) * s1 / den;
    float cb = (1.f - x2) / den;
    float z = ca * mi + cb * bi;
    float s_zz = blockReduceSum(z * z, red);
    float znp = sqrtf(s_zz), zn = fmaxf(znp, 1e-15f);
    float sc = (zn > MAXNORM) ? (MAXNORM / zn) : 1.f;
    float nn = sc * znp;
    if (do_tanh) {
        float nzn = fmaxf(nn, 1e-15f);
        float lsc = atanhf(fminf(nzn, ATANH_LIM)) / nzn * sc;
        float vi = tanhf(lsc * z);
        float s_vv = blockReduceSum(vi * vi, red);
        float vnp = sqrtf(s_vv), vn = fmaxf(vnp, 1e-15f);
        float esc = tanhf(vn) / vn;
        float en  = esc * vnp;
        float pn  = fmaxf(en, 1e-15f);
        float psc = (pn > MAXNORM) ? (MAXNORM / pn) : 1.f;
        if (tid < n) v[tid] = psc * esc * vi;
        nn = psc * esc * vnp;
    } else {
        if (tid < n) v[tid] = sc * z;
    }
    __syncthreads();
    return nn;
}

#define MLP_ROWS 8
__global__ void mlp_kernel(const float* __restrict__ mid, const float* __restrict__ midn,
                           const float* __restrict__ Wm1, const float* __restrict__ bm1,
                           const float* __restrict__ Wm2, const float* __restrict__ bm2,
                           const float* __restrict__ Wm3, const float* __restrict__ bm3,
                           float* __restrict__ out)
{
    __shared__ float sx[256];
    __shared__ float part[256];
    __shared__ float va[64];
    __shared__ float vb[32];
    __shared__ float vc[2];
    __shared__ float red[32];
    int tid = threadIdx.x;
    int r0 = blockIdx.x * MLP_ROWS;
    for (int r = r0; r < r0 + MLP_ROWS; r++) {
        sx[tid] = mid[(size_t)r * 256 + tid];
        float xn = midn[r];
        __syncthreads();
        matvec_sm(sx, 256, Wm1, 64, va, part);
        xn = hlin_epi_sm(va, 64, bm1, xn, true, red);
        matvec_sm(va, 64, Wm2, 32, vb, part);
        xn = hlin_epi_sm(vb, 32, bm2, xn, true, red);
        matvec_sm(vb, 32, Wm3, 2, vc, part);
        xn = hlin_epi_sm(vc, 2, bm3, xn, false, red);
        if (tid < 2) out[(size_t)r * 2 + tid] = vc[tid];
        __syncthreads();
    }
}

// ---------------- host orchestration ----------------
static void run_branch(const float* X, const float* W1t, const float* b1,
                       const float* W2t, const float* b2,
                       const float* W3t, const float* b3,
                       float* MX, float* Y, float* nrm)
{
    const int B = BATCH;
    hgemm<<<dim3(1024 / 128, B / 128), 256, HSMEM>>>(X, W1t, MX, 1024, KP1);
    epi_kernel<1024, true><<<B, 256>>>(MX, b1, nrm, Y, nrm);
    hgemm<<<dim3(512 / 128, B / 128), 256, HSMEM>>>(Y, W2t, MX, 512, 1024);
    epi_kernel<512, true><<<B, 256>>>(MX, b2, nrm, Y, nrm);
    hgemm<<<dim3(256 / 128, B / 128), 256, HSMEM>>>(Y, W3t, MX, 256, 512);
    epi_kernel<256, false><<<B, 256>>>(MX, b3, nrm, Y, nrm);
}

extern "C" void kernel_launch(void* const* d_in, const int* in_sizes, int n_in,
                              void* d_out, int out_size)
{
    const float* dcb  = (const float*)d_in[0];
    const float* dpc  = (const float*)d_in[1];
    const float* dmac = (const float*)d_in[2];
    const float* decf = (const float*)d_in[3];
    const float* tesm = (const float*)d_in[4];
    const float* tpc  = (const float*)d_in[5];
    const float* tmer = (const float*)d_in[6];
    const float* Wd1 = (const float*)d_in[7];  const float* bd1 = (const float*)d_in[8];
    const float* Wd2 = (const float*)d_in[9];  const float* bd2 = (const float*)d_in[10];
    const float* Wd3 = (const float*)d_in[11]; const float* bd3 = (const float*)d_in[12];
    const float* Wt1 = (const float*)d_in[13]; const float* bt1 = (const float*)d_in[14];
    const float* Wt2 = (const float*)d_in[15]; const float* bt2 = (const float*)d_in[16];
    const float* Wt3 = (const float*)d_in[17]; const float* bt3 = (const float*)d_in[18];
    const float* Wm1 = (const float*)d_in[19]; const float* bm1 = (const float*)d_in[20];
    const float* Wm2 = (const float*)d_in[21]; const float* bm2 = (const float*)d_in[22];
    const float* Wm3 = (const float*)d_in[23]; const float* bm3 = (const float*)d_in[24];

    float *Xd, *Xt, *MXd, *MXt, *Yd, *Yt, *nd, *nt, *mid, *nmid;
    float *Wd1t, *Wt1t, *Wd2t, *Wt2t, *Wd3t, *Wt3t;
    cudaGetSymbolAddress((void**)&Xd,   g_Xd);
    cudaGetSymbolAddress((void**)&Xt,   g_Xt);
    cudaGetSymbolAddress((void**)&MXd,  g_MXd);
    cudaGetSymbolAddress((void**)&MXt,  g_MXt);
    cudaGetSymbolAddress((void**)&Yd,   g_Yd);
    cudaGetSymbolAddress((void**)&Yt,   g_Yt);
    cudaGetSymbolAddress((void**)&nd,   g_nd);
    cudaGetSymbolAddress((void**)&nt,   g_nt);
    cudaGetSymbolAddress((void**)&mid,  g_mid);
    cudaGetSymbolAddress((void**)&nmid, g_nmid);
    cudaGetSymbolAddress((void**)&Wd1t, g_Wd1t);
    cudaGetSymbolAddress((void**)&Wt1t, g_Wt1t);
    cudaGetSymbolAddress((void**)&Wd2t, g_Wd2t);
    cudaGetSymbolAddress((void**)&Wt2t, g_Wt2t);
    cudaGetSymbolAddress((void**)&Wd3t, g_Wd3t);
    cudaGetSymbolAddress((void**)&Wt3t, g_Wt3t);

    cudaFuncSetAttribute(hgemm, cudaFuncAttributeMaxDynamicSharedMemorySize, HSMEM);

    const int B = BATCH;
    dim3 tb(32, 8);
    transpose_pad<<<dim3(KP1 / 32, 1024 / 32), tb>>>(Wd1, Wd1t, D_IN, 1024, KP1);
    transpose_pad<<<dim3(KP1 / 32, 1024 / 32), tb>>>(Wt1, Wt1t, D_IN, 1024, KP1);
    transpose_pad<<<dim3(1024 / 32, 512 / 32), tb>>>(Wd2, Wd2t, 1024, 512, 1024);
    transpose_pad<<<dim3(1024 / 32, 512 / 32), tb>>>(Wt2, Wt2t, 1024, 512, 1024);
    transpose_pad<<<dim3(512 / 32, 256 / 32), tb>>>(Wd3, Wd3t, 512, 256, 512);
    transpose_pad<<<dim3(512 / 32, 256 / 32), tb>>>(Wt3, Wt3t, 512, 256, 512);

    pre_kernel<<<B, 256>>>(dcb, 768, dpc, 11, dmac, 167, decf, 765, Xd, nd);
    pre_kernel<<<B, 256>>>(tesm, 1280, tpc, 11, tmer, 420, nullptr, 0, Xt, nt);

    run_branch(Xd, Wd1t, bd1, Wd2t, bd2, Wd3t, bd3, MXd, Yd, nd);
    run_branch(Xt, Wt1t, bt1, Wt2t, bt2, Wt3t, bt3, MXt, Yt, nt);

    combine_kernel<<<B, 256>>>(Yd, Yt, mid, nmid);

    mlp_kernel<<<B / MLP_ROWS, 256>>>(mid, nmid, Wm1, bm1, Wm2, bm2, Wm3, bm3,
                                      (float*)d_out);
}